// round 16
// baseline (speedup 1.0000x reference)
#include <cuda_runtime.h>
#include <math.h>

// KDLayerNorm via Fourier factorization, warp-specialized mode reduction.
// 2*cdf_i - 1 = (1/D) * sum_j erf(xs_i - xs_j),  xs = x/(bw*sqrt2)
// erf(t) = t/L + sum_k beta_k sin(k*pi*t/L),  L=13, K=16 (valid |t| <= 22)
// Pass 1: warp w computes modes {2w+1, 2w+2} over the staged row (MUFU sincos).
// Pass 1.5: lane-0 threads fold (C_k,S_k) into amplitude-phase {rho_k, delta_k}.
// Pass 2: R += rho_k * sin(k*q + delta_k)  -- no serial recurrence chain.
// Epilogue: single-branch Giles erfinv (cdf provably in central range).

#define D 256
#define K 16
#define NW 8
#define TH1 0.2416609734f         // pi/13
#define LINV 0.0769230769f        // 1/13

__constant__ float BETA[K] = {
    0.62740f,  0.30025f,  0.18608f,  0.12600f,
    0.08838f,  0.06273f,  0.04447f,  0.03126f,
    0.02168f,  0.01478f,  0.00990f,  0.00648f,
    0.00415f,  0.00260f,  0.00159f,  0.00095f
};

__device__ __forceinline__ float erfinv_fast(float x) {
    // Giles (2010) central branch; valid for w = -ln(1-x^2) < 5 (|x| < 0.9966).
    float w = -__logf(fmaf(-x, x, 1.0f));
    w = w - 2.5f;
    float p =  2.81022636e-08f;
    p = fmaf(p, w,  3.43273939e-07f);
    p = fmaf(p, w, -3.5233877e-06f);
    p = fmaf(p, w, -4.39150654e-06f);
    p = fmaf(p, w,  2.1858087e-04f);
    p = fmaf(p, w, -1.25372503e-03f);
    p = fmaf(p, w, -4.17768164e-03f);
    p = fmaf(p, w,  2.46640727e-01f);
    p = fmaf(p, w,  1.50140941e+00f);
    return p * x;
}

__global__ __launch_bounds__(D, 8)
void kdln_kernel(const float* __restrict__ x,
                 const float* __restrict__ weight,
                 const float* __restrict__ bias,
                 float* __restrict__ out)
{
    __shared__ __align__(16) float sxs[D];       // staged scaled row
    __shared__ __align__(16) float2 scs[K];      // {rho_k, delta_k}
    __shared__ float red[NW][2];

    const int row  = blockIdx.x;
    const int t    = threadIdx.x;
    const int lane = t & 31;
    const int wid  = t >> 5;

    const float v = x[row * D + t];

    // --- row mean / var (ddof=1) ---
    float s = v, q = v * v;
    #pragma unroll
    for (int o = 16; o > 0; o >>= 1) {
        s += __shfl_xor_sync(0xFFFFFFFFu, s, o);
        q += __shfl_xor_sync(0xFFFFFFFFu, q, o);
    }
    if (lane == 0) { red[wid][0] = s; red[wid][1] = q; }
    __syncthreads();

    float S = 0.f, Q = 0.f;
    #pragma unroll
    for (int i = 0; i < NW; i++) { S += red[i][0]; Q += red[i][1]; }

    const float mean = S * (1.0f / D);
    const float var  = (Q - (float)D * mean * mean) * (1.0f / (D - 1));
    // bw*sqrt2 = 0.9*256^(-0.2)*sqrt(2)*std = 0.419866*std
    const float inv  = 1.0f / (0.419866213f * sqrtf(var));

    const float xs = v * inv;
    const float SX = S * inv;

    sxs[t] = xs;
    __syncthreads();

    // --- pass 1: warp-specialized mode sums (2 modes per warp) ---
    {
        const float4* p4 = (const float4*)sxs;
        const float4 a = p4[lane * 2];
        const float4 b = p4[lane * 2 + 1];

        #pragma unroll
        for (int m = 0; m < 2; m++) {
            const int ki = 2 * wid + m;        // 0..15 -> k = ki+1
            const float th = (float)(ki + 1) * TH1;
            float as = 0.f, ac = 0.f;
            {
                float p;
                p = th * a.x; as += __sinf(p); ac += __cosf(p);
                p = th * a.y; as += __sinf(p); ac += __cosf(p);
                p = th * a.z; as += __sinf(p); ac += __cosf(p);
                p = th * a.w; as += __sinf(p); ac += __cosf(p);
                p = th * b.x; as += __sinf(p); ac += __cosf(p);
                p = th * b.y; as += __sinf(p); ac += __cosf(p);
                p = th * b.z; as += __sinf(p); ac += __cosf(p);
                p = th * b.w; as += __sinf(p); ac += __cosf(p);
            }
            #pragma unroll
            for (int o = 16; o > 0; o >>= 1) {
                as += __shfl_xor_sync(0xFFFFFFFFu, as, o);
                ac += __shfl_xor_sync(0xFFFFFFFFu, ac, o);
            }
            if (lane == 0) {
                // amplitude-phase fold: beta*(C sin(kq) - S cos(kq)) = rho*sin(kq+delta)
                const float rho   = BETA[ki] * sqrtf(fmaf(ac, ac, as * as));
                const float delta = atan2f(-as, ac);
                scs[ki] = make_float2(rho, delta);
            }
        }
    }
    __syncthreads();

    // --- pass 2: R += rho_k * sin(k*q + delta_k), fully parallel ---
    const float qq = TH1 * xs;
    float R = (256.0f * xs - SX) * LINV;
    {
        const float4* scs4 = (const float4*)scs;   // {rho_k, del_k, rho_{k+1}, del_{k+1}}
        #pragma unroll
        for (int j = 0; j < K / 2; j++) {
            const float4 cs = scs4[j];
            const float k0 = (float)(2 * j + 1);
            const float k1 = (float)(2 * j + 2);
            R = fmaf(cs.x, __sinf(fmaf(k0, qq, cs.y)), R);
            R = fmaf(cs.z, __sinf(fmaf(k1, qq, cs.w)), R);
        }
    }

    // 2*cdf - 1 = R / D  (guaranteed central branch)
    float w2 = R * (1.0f / D);
    w2 = fminf(fmaxf(w2, -0.9965f), 0.9965f);
    const float nrm = erfinv_fast(w2) * 1.4142135623730951f;
    out[row * D + t] = nrm * weight[t] + bias[t];
}

extern "C" void kernel_launch(void* const* d_in, const int* in_sizes, int n_in,
                              void* d_out, int out_size)
{
    const float* x = (const float*)d_in[0];
    const float* w = (const float*)d_in[1];
    const float* b = (const float*)d_in[2];
    float* out = (float*)d_out;

    const int n_rows = in_sizes[0] / D;   // 4096
    kdln_kernel<<<n_rows, D>>>(x, w, b, out);
}

// round 17
// speedup vs baseline: 1.2405x; 1.2405x over previous
#include <cuda_runtime.h>
#include <math.h>

// KDLayerNorm via Fourier factorization, warp-specialized mode reduction.
// 2*cdf_i - 1 = (1/D) * sum_j erf(xs_i - xs_j),  xs = x/(bw*sqrt2)
// erf(t) = t/L + sum_k beta_k sin(k*pi*t/L),  L=13, K=16 (valid |t| <= 22)
// Pass 1: warp w computes modes {2w+1, 2w+2} (MUFU sincos, f32 warp reduction).
// Pass 2: Clenshaw recurrence (two chains sharing 2cos q) combines
//         sum_k [A_k sin(kq) + B_k cos(kq)], A_k = beta*C_k, B_k = -beta*S_k.
// Epilogue: single-branch Giles erfinv (cdf provably in central range).

#define D 256
#define K 16
#define NW 8
#define TH1 0.2416609734f         // pi/13
#define LINV 0.0769230769f        // 1/13

__constant__ float BETA[K] = {
    0.62740f,  0.30025f,  0.18608f,  0.12600f,
    0.08838f,  0.06273f,  0.04447f,  0.03126f,
    0.02168f,  0.01478f,  0.00990f,  0.00648f,
    0.00415f,  0.00260f,  0.00159f,  0.00095f
};

__device__ __forceinline__ float erfinv_fast(float x) {
    // Giles (2010) central branch; valid for w = -ln(1-x^2) < 5 (|x| < 0.9966).
    float w = -__logf(fmaf(-x, x, 1.0f));
    w = w - 2.5f;
    float p =  2.81022636e-08f;
    p = fmaf(p, w,  3.43273939e-07f);
    p = fmaf(p, w, -3.5233877e-06f);
    p = fmaf(p, w, -4.39150654e-06f);
    p = fmaf(p, w,  2.1858087e-04f);
    p = fmaf(p, w, -1.25372503e-03f);
    p = fmaf(p, w, -4.17768164e-03f);
    p = fmaf(p, w,  2.46640727e-01f);
    p = fmaf(p, w,  1.50140941e+00f);
    return p * x;
}

__global__ __launch_bounds__(D, 8)
void kdln_kernel(const float* __restrict__ x,
                 const float* __restrict__ weight,
                 const float* __restrict__ bias,
                 float* __restrict__ out)
{
    __shared__ __align__(16) float sxs[D];       // staged scaled row
    __shared__ __align__(16) float2 scs[K];      // {A_k, B_k} = {b*C_k, -b*S_k}
    __shared__ float red[NW][2];

    const int row  = blockIdx.x;
    const int t    = threadIdx.x;
    const int lane = t & 31;
    const int wid  = t >> 5;

    const float v = x[row * D + t];

    // --- row mean / var (ddof=1) ---
    float s = v, q = v * v;
    #pragma unroll
    for (int o = 16; o > 0; o >>= 1) {
        s += __shfl_xor_sync(0xFFFFFFFFu, s, o);
        q += __shfl_xor_sync(0xFFFFFFFFu, q, o);
    }
    if (lane == 0) { red[wid][0] = s; red[wid][1] = q; }
    __syncthreads();

    float S = 0.f, Q = 0.f;
    #pragma unroll
    for (int i = 0; i < NW; i++) { S += red[i][0]; Q += red[i][1]; }

    const float mean = S * (1.0f / D);
    const float var  = (Q - (float)D * mean * mean) * (1.0f / (D - 1));
    // bw*sqrt2 = 0.9*256^(-0.2)*sqrt(2)*std = 0.419866*std
    const float inv  = 1.0f / (0.419866213f * sqrtf(var));

    const float xs = v * inv;
    const float SX = S * inv;

    sxs[t] = xs;
    __syncthreads();

    // --- pass 1: warp-specialized mode sums (2 modes per warp, uniform) ---
    {
        const float4* p4 = (const float4*)sxs;
        const float4 a = p4[lane * 2];
        const float4 b = p4[lane * 2 + 1];

        #pragma unroll
        for (int m = 0; m < 2; m++) {
            const int ki = 2 * wid + m;        // 0..15 -> k = ki+1
            const float th = (float)(ki + 1) * TH1;
            float as = 0.f, ac = 0.f;
            {
                float p;
                p = th * a.x; as += __sinf(p); ac += __cosf(p);
                p = th * a.y; as += __sinf(p); ac += __cosf(p);
                p = th * a.z; as += __sinf(p); ac += __cosf(p);
                p = th * a.w; as += __sinf(p); ac += __cosf(p);
                p = th * b.x; as += __sinf(p); ac += __cosf(p);
                p = th * b.y; as += __sinf(p); ac += __cosf(p);
                p = th * b.z; as += __sinf(p); ac += __cosf(p);
                p = th * b.w; as += __sinf(p); ac += __cosf(p);
            }
            #pragma unroll
            for (int o = 16; o > 0; o >>= 1) {
                as += __shfl_xor_sync(0xFFFFFFFFu, as, o);
                ac += __shfl_xor_sync(0xFFFFFFFFu, ac, o);
            }
            if (lane == 0) {
                const float bk = BETA[ki];
                scs[ki] = make_float2(bk * ac, -bk * as);  // {A_k, B_k}
            }
        }
    }
    __syncthreads();

    // --- pass 2: Clenshaw combine of sum_k [A_k sin(kq) + B_k cos(kq)] ---
    const float qq = TH1 * xs;
    const float s1 = __sinf(qq);
    const float c1 = __cosf(qq);
    const float twoc = 2.0f * c1;

    float uA1 = 0.f, uA2 = 0.f;   // sine-series chain
    float uB1 = 0.f, uB2 = 0.f;   // cosine-series chain
    {
        #pragma unroll
        for (int ki = K - 1; ki >= 0; ki--) {
            const float2 ab = scs[ki];
            const float nA = fmaf(twoc, uA1, ab.x - uA2);
            const float nB = fmaf(twoc, uB1, ab.y - uB2);
            uA2 = uA1; uA1 = nA;
            uB2 = uB1; uB1 = nB;
        }
    }
    // sine series  = s1 * uA1
    // cosine series (a_0 = 0) = c1 * uB1 - uB2
    float R = (256.0f * xs - SX) * LINV;
    R = fmaf(s1, uA1, R);
    R = fmaf(c1, uB1, R);
    R -= uB2;

    // 2*cdf - 1 = R / D  (guaranteed central branch)
    float w2 = R * (1.0f / D);
    w2 = fminf(fmaxf(w2, -0.9965f), 0.9965f);
    const float nrm = erfinv_fast(w2) * 1.4142135623730951f;
    out[row * D + t] = nrm * weight[t] + bias[t];
}

extern "C" void kernel_launch(void* const* d_in, const int* in_sizes, int n_in,
                              void* d_out, int out_size)
{
    const float* x = (const float*)d_in[0];
    const float* w = (const float*)d_in[1];
    const float* b = (const float*)d_in[2];
    float* out = (float*)d_out;

    const int n_rows = in_sizes[0] / D;   // 4096
    kdln_kernel<<<n_rows, D>>>(x, w, b, out);
}